// round 1
// baseline (speedup 1.0000x reference)
#include <cuda_runtime.h>
#include <cstdint>

// Problem constants
#define M_ROWS   4096
#define K_DIM    784
#define N_BASAL  16384
#define NUM_CLS  10
#define NUM_ACT  492   // top-k

// ---------------------------------------------------------------------------
// Scratch: __device__ globals (allocation inside kernel_launch is forbidden)
// ---------------------------------------------------------------------------
__device__ float        g_act[(size_t)M_ROWS * N_BASAL];   // 256 MB activations
__device__ unsigned int g_mask[N_BASAL];                   // packed synapse bits

// ---------------------------------------------------------------------------
// Kernel 0: pack basal_synapses [10,16384] (0/1 floats) into bitmask per column
// ---------------------------------------------------------------------------
__global__ void pack_syn_kernel(const float* __restrict__ syn) {
    int j = blockIdx.x * blockDim.x + threadIdx.x;
    if (j < N_BASAL) {
        unsigned int m = 0;
#pragma unroll
        for (int c = 0; c < NUM_CLS; ++c)
            m |= (syn[c * N_BASAL + j] > 0.5f) ? (1u << c) : 0u;
        g_mask[j] = m;
    }
}

// ---------------------------------------------------------------------------
// Kernel 1: fp32 SGEMM  C[M,N] = A[M,K] * B[K,N]
//   BM=BN=128, BK=8, 256 threads, 8x8 per-thread microtile, reg prefetch
// ---------------------------------------------------------------------------
#define BM 128
#define BN 128
#define BK 8

__global__ __launch_bounds__(256, 2)
void sgemm_kernel(const float* __restrict__ A, const float* __restrict__ B) {
    __shared__ float As[BK][BM];
    __shared__ float Bs[BK][BN];

    const int tid = threadIdx.x;
    const int bx = blockIdx.x;   // N tile
    const int by = blockIdx.y;   // M tile
    const int tx = tid & 15;     // 16 cols of threads
    const int ty = tid >> 4;     // 16 rows of threads

    // A tile load mapping: 128 rows x 8 cols = 256 float4
    const int aRow = tid >> 1;
    const int aCol = (tid & 1) * 4;
    const float* Aptr = A + (size_t)(by * BM + aRow) * K_DIM + aCol;

    // B tile load mapping: 8 rows x 128 cols = 256 float4
    const int bRow = tid >> 5;
    const int bCol = (tid & 31) * 4;
    const float* Bptr = B + (size_t)bRow * N_BASAL + bx * BN + bCol;

    float acc[8][8];
#pragma unroll
    for (int i = 0; i < 8; ++i)
#pragma unroll
        for (int j = 0; j < 8; ++j) acc[i][j] = 0.0f;

    float4 av = *(const float4*)(Aptr);
    float4 bv = *(const float4*)(Bptr);

    for (int k0 = 0; k0 < K_DIM; k0 += BK) {
        // stage current tile into smem
        As[aCol + 0][aRow] = av.x;
        As[aCol + 1][aRow] = av.y;
        As[aCol + 2][aRow] = av.z;
        As[aCol + 3][aRow] = av.w;
        *(float4*)&Bs[bRow][bCol] = bv;
        __syncthreads();

        // prefetch next tile into registers (overlaps with FMA below)
        if (k0 + BK < K_DIM) {
            av = *(const float4*)(Aptr + (k0 + BK));
            bv = *(const float4*)(Bptr + (size_t)(k0 + BK) * N_BASAL);
        }

#pragma unroll
        for (int kk = 0; kk < BK; ++kk) {
            float ar[8], br[8];
            *(float4*)(ar)     = *(const float4*)&As[kk][ty * 8];
            *(float4*)(ar + 4) = *(const float4*)&As[kk][ty * 8 + 4];
            *(float4*)(br)     = *(const float4*)&Bs[kk][tx * 8];
            *(float4*)(br + 4) = *(const float4*)&Bs[kk][tx * 8 + 4];
#pragma unroll
            for (int i = 0; i < 8; ++i)
#pragma unroll
                for (int j = 0; j < 8; ++j)
                    acc[i][j] = fmaf(ar[i], br[j], acc[i][j]);
        }
        __syncthreads();
    }

    // write C
    const int cRow0 = by * BM + ty * 8;
    const int cCol0 = bx * BN + tx * 8;
#pragma unroll
    for (int i = 0; i < 8; ++i) {
        float* crow = g_act + (size_t)(cRow0 + i) * N_BASAL + cCol0;
        *(float4*)(crow)     = make_float4(acc[i][0], acc[i][1], acc[i][2], acc[i][3]);
        *(float4*)(crow + 4) = make_float4(acc[i][4], acc[i][5], acc[i][6], acc[i][7]);
    }
}

// ---------------------------------------------------------------------------
// Kernel 2: per-row exact top-k threshold (3-pass radix select on ordered
// uint keys) + class-overlap accumulation via packed masks.
// One block (256 threads) per row.
// ---------------------------------------------------------------------------
__device__ __forceinline__ unsigned int f2key(float f) {
    unsigned int u = __float_as_uint(f);
    return (u & 0x80000000u) ? ~u : (u | 0x80000000u);   // monotone: bigger f -> bigger key
}

__global__ __launch_bounds__(256)
void select_overlap_kernel(float* __restrict__ out) {
    const int row = blockIdx.x;
    const float* a = g_act + (size_t)row * N_BASAL;
    const int tid = threadIdx.x;

    __shared__ unsigned int hist[2048];
    __shared__ unsigned int segsum[256];
    __shared__ unsigned int s_kk;      // remaining rank within current bin set
    __shared__ unsigned int s_prefix;  // selected high bits so far
    __shared__ unsigned int s_E;       // count equal to final threshold
    __shared__ int ov[NUM_CLS];

    if (tid == 0) { s_kk = NUM_ACT; s_prefix = 0; }
    for (int i = tid; i < NUM_CLS; i += 256) ov[i] = 0;
    __syncthreads();

    // ---- 3 radix passes: digits of 11, 11, 10 bits (MSB first) ----
    for (int p = 0; p < 3; ++p) {
        const int nbins = (p == 2) ? 1024 : 2048;
        for (int i = tid; i < nbins; i += 256) hist[i] = 0;
        __syncthreads();
        const unsigned int prefix = s_prefix;

        for (int j = tid; j < N_BASAL; j += 256) {
            unsigned int key = f2key(a[j]);
            unsigned int d; bool ok;
            if (p == 0)      { ok = true;                       d = key >> 21; }
            else if (p == 1) { ok = ((key >> 21) == prefix);    d = (key >> 10) & 2047u; }
            else             { ok = ((key >> 10) == prefix);    d = key & 1023u; }
            if (ok) atomicAdd(&hist[d], 1u);
        }
        __syncthreads();

        // descending two-level scan to find the bin holding the s_kk-th key
        const int seg = nbins / 256;
        unsigned int ssum = 0;
        for (int i = 0; i < seg; ++i) ssum += hist[nbins - 1 - (tid * seg + i)];
        segsum[tid] = ssum;
        __syncthreads();

        if (tid == 0) {
            unsigned int kk = s_kk;
            unsigned int before = 0;
            int selseg = 255;
            for (int t = 0; t < 256; ++t) {
                if (before + segsum[t] >= kk) { selseg = t; break; }
                before += segsum[t];
            }
            int selbin = 0;
            for (int i = 0; i < seg; ++i) {
                int b = nbins - 1 - (selseg * seg + i);
                unsigned int c = hist[b];
                if (before + c >= kk) { selbin = b; break; }
                before += c;
            }
            s_kk = kk - before;          // rank remaining inside selected bin
            s_E  = hist[selbin];
            if (p == 0)      s_prefix = (unsigned int)selbin;
            else if (p == 1) s_prefix = (prefix << 11) | (unsigned int)selbin;
            else             s_prefix = (prefix << 10) | (unsigned int)selbin; // = full key
        }
        __syncthreads();
    }

    const unsigned int tkey = s_prefix;   // exact key of 492nd largest
    const unsigned int r    = s_kk;       // # of equals to include (index order)
    const unsigned int E    = s_E;        // total equals
    const bool inclEq = (r == E);         // common case: include all equals

    // ---- inclusion pass: accumulate per-class counts ----
    int cnt[NUM_CLS];
#pragma unroll
    for (int c = 0; c < NUM_CLS; ++c) cnt[c] = 0;

    for (int j = tid; j < N_BASAL; j += 256) {
        unsigned int key = f2key(a[j]);
        if (key > tkey || (inclEq && key == tkey)) {
            unsigned int m = g_mask[j];
#pragma unroll
            for (int c = 0; c < NUM_CLS; ++c) cnt[c] += (m >> c) & 1u;
        }
    }
#pragma unroll
    for (int c = 0; c < NUM_CLS; ++c)
        if (cnt[c]) atomicAdd(&ov[c], cnt[c]);
    __syncthreads();

    // rare tie slow path: take first r equals in ascending index order
    if (!inclEq && tid == 0) {
        unsigned int taken = 0;
        for (int j = 0; j < N_BASAL && taken < r; ++j) {
            if (f2key(a[j]) == tkey) {
                unsigned int m = g_mask[j];
                for (int c = 0; c < NUM_CLS; ++c) ov[c] += (int)((m >> c) & 1u);
                ++taken;
            }
        }
    }
    __syncthreads();

    if (tid < NUM_CLS)
        out[row * NUM_CLS + tid] = (float)ov[tid];
}

// ---------------------------------------------------------------------------
// Launch
// ---------------------------------------------------------------------------
extern "C" void kernel_launch(void* const* d_in, const int* in_sizes, int n_in,
                              void* d_out, int out_size) {
    const float* image = (const float*)d_in[0];   // [4096, 784]
    const float* proj  = (const float*)d_in[1];   // [784, 16384]
    const float* syn   = (const float*)d_in[2];   // [10, 16384]
    float* out = (float*)d_out;                   // [4096, 10]

    pack_syn_kernel<<<(N_BASAL + 255) / 256, 256>>>(syn);
    dim3 grid(N_BASAL / BN, M_ROWS / BM);         // 128 x 32
    sgemm_kernel<<<grid, 256>>>(image, proj);
    select_overlap_kernel<<<M_ROWS, 256>>>(out);
}

// round 4
// speedup vs baseline: 1.7087x; 1.7087x over previous
#include <cuda_runtime.h>
#include <cuda_bf16.h>
#include <cstdint>

// ---------------- problem constants ----------------
#define M_ROWS   4096
#define K_DIM    784
#define K_PAD    2368          // 3*784 = 2352, padded to 74*32
#define N_BASAL  16384
#define NUM_CLS  10
#define NUM_ACT  492

// ---------------- GEMM tiling ----------------
#define BM 128
#define BN 128
#define BK 32
#define NCHUNK (K_PAD / BK)    // 74
#define NSTAGE 3
#define ROW_BYTES 80           // 64B data + 16B skew (bank-conflict-free)
#define A_STAGE_BYTES (BM * ROW_BYTES)   // 10240
#define B_STAGE_BYTES (BN * ROW_BYTES)   // 10240
#define STAGE_BYTES (A_STAGE_BYTES + B_STAGE_BYTES)
#define SMEM_TOTAL (NSTAGE * STAGE_BYTES)   // 61440

// ---------------- scratch (device globals; no allocs allowed) ----------------
__device__ float          g_act[(size_t)M_ROWS * N_BASAL];     // 256 MB
__device__ unsigned int   g_mask[N_BASAL];
__device__ __nv_bfloat16  g_A[(size_t)M_ROWS * K_PAD];         // [Ah|Al|Ah|0]
__device__ __nv_bfloat16  g_B[(size_t)N_BASAL * K_PAD];        // [n][k]: [Bh|Bh|Bl|0]

// ---------------- asm helpers ----------------
__device__ __forceinline__ uint32_t smem_u32(const void* p) {
    uint32_t a;
    asm("{ .reg .u64 t; cvta.to.shared.u64 t, %1; cvt.u32.u64 %0, t; }" : "=r"(a) : "l"(p));
    return a;
}
__device__ __forceinline__ void cp_async16(uint32_t dst, const void* src) {
    asm volatile("cp.async.cg.shared.global [%0], [%1], 16;" :: "r"(dst), "l"(src) : "memory");
}
__device__ __forceinline__ void cp_commit() {
    asm volatile("cp.async.commit_group;" ::: "memory");
}
template <int N>
__device__ __forceinline__ void cp_wait() {
    asm volatile("cp.async.wait_group %0;" :: "n"(N) : "memory");
}
__device__ __forceinline__ void ldm_x4(uint32_t* r, uint32_t addr) {
    asm volatile("ldmatrix.sync.aligned.m8n8.x4.shared.b16 {%0,%1,%2,%3}, [%4];"
                 : "=r"(r[0]), "=r"(r[1]), "=r"(r[2]), "=r"(r[3]) : "r"(addr));
}
__device__ __forceinline__ void mma_bf16(float* c, const uint32_t* a, uint32_t b0, uint32_t b1) {
    asm volatile("mma.sync.aligned.m16n8k16.row.col.f32.bf16.bf16.f32 "
                 "{%0,%1,%2,%3}, {%4,%5,%6,%7}, {%8,%9}, {%0,%1,%2,%3};"
                 : "+f"(c[0]), "+f"(c[1]), "+f"(c[2]), "+f"(c[3])
                 : "r"(a[0]), "r"(a[1]), "r"(a[2]), "r"(a[3]), "r"(b0), "r"(b1));
}

// ---------------------------------------------------------------------------
// Kernel: pack synapses into bitmasks
// ---------------------------------------------------------------------------
__global__ void pack_syn_kernel(const float* __restrict__ syn) {
    int j = blockIdx.x * blockDim.x + threadIdx.x;
    if (j < N_BASAL) {
        unsigned int m = 0;
#pragma unroll
        for (int c = 0; c < NUM_CLS; ++c)
            m |= (syn[c * N_BASAL + j] > 0.5f) ? (1u << c) : 0u;
        g_mask[j] = m;
    }
}

// ---------------------------------------------------------------------------
// Kernel: build A' = [Ah | Al | Ah | 0]  (bf16, K-major)
// ---------------------------------------------------------------------------
__global__ void conv_a_kernel(const float* __restrict__ img) {
    size_t idx = (size_t)blockIdx.x * 256 + threadIdx.x;
    int m = (int)(idx / K_PAD);
    int k = (int)(idx % K_PAD);
    __nv_bfloat16 r;
    if (k < K_DIM) {
        r = __float2bfloat16(img[(size_t)m * K_DIM + k]);
    } else if (k < 2 * K_DIM) {
        float v = img[(size_t)m * K_DIM + (k - K_DIM)];
        __nv_bfloat16 h = __float2bfloat16(v);
        r = __float2bfloat16(v - __bfloat162float(h));
    } else if (k < 3 * K_DIM) {
        r = __float2bfloat16(img[(size_t)m * K_DIM + (k - 2 * K_DIM)]);
    } else {
        r = __float2bfloat16(0.0f);
    }
    g_A[idx] = r;
}

// ---------------------------------------------------------------------------
// Kernel: build B' rows (transpose proj): g_B[n][k'] = [Bh | Bh | Bl]
// ---------------------------------------------------------------------------
__global__ void conv_b_kernel(const float* __restrict__ proj) {
    __shared__ float t[32][33];
    int k0 = blockIdx.x * 32, n0 = blockIdx.y * 32;
    int tx = threadIdx.x, ty = threadIdx.y;   // 32 x 8
#pragma unroll
    for (int i = 0; i < 32; i += 8) {
        int kk = k0 + ty + i;
        t[ty + i][tx] = (kk < K_DIM) ? proj[(size_t)kk * N_BASAL + n0 + tx] : 0.0f;
    }
    __syncthreads();
#pragma unroll
    for (int i = 0; i < 32; i += 8) {
        int n = n0 + ty + i;
        int k = k0 + tx;
        if (k < K_DIM) {
            float v = t[tx][ty + i];
            __nv_bfloat16 h = __float2bfloat16(v);
            __nv_bfloat16 l = __float2bfloat16(v - __bfloat162float(h));
            size_t base = (size_t)n * K_PAD;
            g_B[base + k]             = h;
            g_B[base + k + K_DIM]     = h;
            g_B[base + k + 2 * K_DIM] = l;
        }
    }
}

__global__ void pad_b_kernel() {
    int idx = blockIdx.x * 256 + threadIdx.x;   // 16384 * 16
    int n = idx >> 4;
    int k = 3 * K_DIM + (idx & 15);
    g_B[(size_t)n * K_PAD + k] = __float2bfloat16(0.0f);
}

// ---------------------------------------------------------------------------
// mma.sync bf16 GEMM: g_act[M,N] = g_A[M,Kp] * g_B[N,Kp]^T  (fp32 accum)
//   256 threads = 8 warps (2x4), warp tile 64x32, BK=32, 3-stage cp.async
// ---------------------------------------------------------------------------
__global__ __launch_bounds__(256, 2)
void gemm_mma_kernel() {
    extern __shared__ char smem[];
    const uint32_t sb = smem_u32(smem);
    const int tid = threadIdx.x;
    const int lane = tid & 31;
    const int wid = tid >> 5;
    const int warpM = wid >> 2;          // 0..1
    const int warpN = wid & 3;           // 0..3
    const int m0 = blockIdx.y * BM;
    const int n0 = blockIdx.x * BN;

    const char* Abase = (const char*)g_A + (size_t)m0 * (K_PAD * 2);
    const char* Bbase = (const char*)g_B + (size_t)n0 * (K_PAD * 2);

    // cp.async mapping: thread t covers chunks t and t+256 of [A(512) | B(512)]
    const int ar  = tid >> 2;            // A row 0..63 (first half), +64 second
    const int ac  = tid & 3;             // 16B chunk within 64B row

    auto load_stage = [&](int c, int s) {
        const uint32_t st = sb + s * STAGE_BYTES;
        const size_t koff = (size_t)c * (BK * 2);
        cp_async16(st + ar * ROW_BYTES + ac * 16,
                   Abase + (size_t)ar * (K_PAD * 2) + koff + ac * 16);
        cp_async16(st + (ar + 64) * ROW_BYTES + ac * 16,
                   Abase + (size_t)(ar + 64) * (K_PAD * 2) + koff + ac * 16);
        const uint32_t stB = st + A_STAGE_BYTES;
        cp_async16(stB + ar * ROW_BYTES + ac * 16,
                   Bbase + (size_t)ar * (K_PAD * 2) + koff + ac * 16);
        cp_async16(stB + (ar + 64) * ROW_BYTES + ac * 16,
                   Bbase + (size_t)(ar + 64) * (K_PAD * 2) + koff + ac * 16);
        cp_commit();
    };

    float acc[4][4][4];
#pragma unroll
    for (int i = 0; i < 4; ++i)
#pragma unroll
        for (int j = 0; j < 4; ++j)
#pragma unroll
            for (int q = 0; q < 4; ++q) acc[i][j][q] = 0.0f;

    const int lrow = lane & 15;
    const int lcol16 = (lane >> 4) << 4;   // 0 or 16 bytes

    load_stage(0, 0);
    load_stage(1, 1);

    for (int c = 0; c < NCHUNK; ++c) {
        const int s = c % NSTAGE;
        cp_wait<NSTAGE - 2>();
        __syncthreads();
        if (c + 2 < NCHUNK) load_stage(c + 2, (c + 2) % NSTAGE);

        const uint32_t stA = sb + s * STAGE_BYTES;
        const uint32_t stB = stA + A_STAGE_BYTES;
#pragma unroll
        for (int ks = 0; ks < 2; ++ks) {
            const int kbyte = ks * 32 + lcol16;
            uint32_t af[4][4];
#pragma unroll
            for (int mt = 0; mt < 4; ++mt)
                ldm_x4(af[mt], stA + (warpM * 64 + mt * 16 + lrow) * ROW_BYTES + kbyte);
            uint32_t bf[2][4];
#pragma unroll
            for (int nt = 0; nt < 2; ++nt)
                ldm_x4(bf[nt], stB + (warpN * 32 + nt * 16 + lrow) * ROW_BYTES + kbyte);
#pragma unroll
            for (int mt = 0; mt < 4; ++mt) {
#pragma unroll
                for (int n8 = 0; n8 < 4; ++n8) {
                    const int nt = n8 >> 1, hi = n8 & 1;
                    mma_bf16(acc[mt][n8], af[mt], bf[nt][hi], bf[nt][hi + 2]);
                }
            }
        }
        __syncthreads();
    }

    // epilogue
    const int grp = lane >> 2;
    const int tj  = lane & 3;
#pragma unroll
    for (int mt = 0; mt < 4; ++mt) {
#pragma unroll
        for (int n8 = 0; n8 < 4; ++n8) {
            const int row = m0 + warpM * 64 + mt * 16 + grp;
            const int col = n0 + warpN * 32 + n8 * 8 + tj * 2;
            float* p0 = g_act + (size_t)row * N_BASAL + col;
            float* p1 = g_act + (size_t)(row + 8) * N_BASAL + col;
            *(float2*)p0 = make_float2(acc[mt][n8][0], acc[mt][n8][1]);
            *(float2*)p1 = make_float2(acc[mt][n8][2], acc[mt][n8][3]);
        }
    }
}

// ---------------------------------------------------------------------------
// Kernel: per-row exact top-k threshold (radix select) + class overlap
// ---------------------------------------------------------------------------
__device__ __forceinline__ unsigned int f2key(float f) {
    unsigned int u = __float_as_uint(f);
    return (u & 0x80000000u) ? ~u : (u | 0x80000000u);
}

__global__ __launch_bounds__(256)
void select_overlap_kernel(float* __restrict__ out) {
    const int row = blockIdx.x;
    const float* a = g_act + (size_t)row * N_BASAL;
    const int tid = threadIdx.x;

    __shared__ unsigned int hist[2048];
    __shared__ unsigned int segsum[256];
    __shared__ unsigned int s_kk, s_prefix, s_E;
    __shared__ int ov[NUM_CLS];

    if (tid == 0) { s_kk = NUM_ACT; s_prefix = 0; }
    for (int i = tid; i < NUM_CLS; i += 256) ov[i] = 0;
    __syncthreads();

    for (int p = 0; p < 3; ++p) {
        const int nbins = (p == 2) ? 1024 : 2048;
        for (int i = tid; i < nbins; i += 256) hist[i] = 0;
        __syncthreads();
        const unsigned int prefix = s_prefix;

        for (int j = tid; j < N_BASAL; j += 256) {
            unsigned int key = f2key(a[j]);
            unsigned int d; bool ok;
            if (p == 0)      { ok = true;                    d = key >> 21; }
            else if (p == 1) { ok = ((key >> 21) == prefix); d = (key >> 10) & 2047u; }
            else             { ok = ((key >> 10) == prefix); d = key & 1023u; }
            if (ok) atomicAdd(&hist[d], 1u);
        }
        __syncthreads();

        const int seg = nbins / 256;
        unsigned int ssum = 0;
        for (int i = 0; i < seg; ++i) ssum += hist[nbins - 1 - (tid * seg + i)];
        segsum[tid] = ssum;
        __syncthreads();

        if (tid == 0) {
            unsigned int kk = s_kk, before = 0;
            int selseg = 255;
            for (int t = 0; t < 256; ++t) {
                if (before + segsum[t] >= kk) { selseg = t; break; }
                before += segsum[t];
            }
            int selbin = 0;
            for (int i = 0; i < seg; ++i) {
                int b = nbins - 1 - (selseg * seg + i);
                unsigned int ccount = hist[b];
                if (before + ccount >= kk) { selbin = b; break; }
                before += ccount;
            }
            s_kk = kk - before;
            s_E  = hist[selbin];
            if (p == 0)      s_prefix = (unsigned int)selbin;
            else if (p == 1) s_prefix = (prefix << 11) | (unsigned int)selbin;
            else             s_prefix = (prefix << 10) | (unsigned int)selbin;
        }
        __syncthreads();
    }

    const unsigned int tkey = s_prefix;
    const unsigned int r    = s_kk;
    const unsigned int E    = s_E;
    const bool inclEq = (r == E);

    int cnt[NUM_CLS];
#pragma unroll
    for (int c = 0; c < NUM_CLS; ++c) cnt[c] = 0;

    for (int j = tid; j < N_BASAL; j += 256) {
        unsigned int key = f2key(a[j]);
        if (key > tkey || (inclEq && key == tkey)) {
            unsigned int m = g_mask[j];
#pragma unroll
            for (int c = 0; c < NUM_CLS; ++c) cnt[c] += (m >> c) & 1u;
        }
    }
#pragma unroll
    for (int c = 0; c < NUM_CLS; ++c)
        if (cnt[c]) atomicAdd(&ov[c], cnt[c]);
    __syncthreads();

    if (!inclEq && tid == 0) {
        unsigned int taken = 0;
        for (int j = 0; j < N_BASAL && taken < r; ++j) {
            if (f2key(a[j]) == tkey) {
                unsigned int m = g_mask[j];
                for (int c = 0; c < NUM_CLS; ++c) ov[c] += (int)((m >> c) & 1u);
                ++taken;
            }
        }
    }
    __syncthreads();

    if (tid < NUM_CLS)
        out[row * NUM_CLS + tid] = (float)ov[tid];
}

// ---------------------------------------------------------------------------
// Launch
// ---------------------------------------------------------------------------
extern "C" void kernel_launch(void* const* d_in, const int* in_sizes, int n_in,
                              void* d_out, int out_size) {
    const float* image = (const float*)d_in[0];   // [4096, 784]
    const float* proj  = (const float*)d_in[1];   // [784, 16384]
    const float* syn   = (const float*)d_in[2];   // [10, 16384]
    float* out = (float*)d_out;                   // [4096, 10]

    cudaFuncSetAttribute(gemm_mma_kernel, cudaFuncAttributeMaxDynamicSharedMemorySize, SMEM_TOTAL);

    pack_syn_kernel<<<(N_BASAL + 255) / 256, 256>>>(syn);
    conv_a_kernel<<<(int)(((size_t)M_ROWS * K_PAD) / 256), 256>>>(image);
    {
        dim3 grid((K_DIM + 31) / 32, N_BASAL / 32);
        conv_b_kernel<<<grid, dim3(32, 8)>>>(proj);
    }
    pad_b_kernel<<<(N_BASAL * 16) / 256, 256>>>();
    {
        dim3 grid(N_BASAL / BN, M_ROWS / BM);     // 128 x 32
        gemm_mma_kernel<<<grid, 256, SMEM_TOTAL>>>();
    }
    select_overlap_kernel<<<M_ROWS, 256>>>(out);
}

// round 5
// speedup vs baseline: 2.6992x; 1.5797x over previous
#include <cuda_runtime.h>
#include <cuda_bf16.h>
#include <cstdint>

// ---------------- problem constants ----------------
#define M_ROWS   4096
#define K_DIM    784
#define K_PAD    800           // 784 padded to 25*32
#define N_BASAL  16384
#define NUM_CLS  10
#define NUM_ACT  492
#define DELTA    0.03f         // margin for bf16 GEMM error (~6.5 sigma)
#define MAXC     384           // candidate buffer per row

// ---------------- GEMM tiling ----------------
#define BM 128
#define BN 128
#define BK 32
#define NCHUNK (K_PAD / BK)    // 25
#define NSTAGE 3
#define ROW_BYTES 80           // 64B data + 16B skew (bank-conflict-free)
#define A_STAGE_BYTES (BM * ROW_BYTES)
#define B_STAGE_BYTES (BN * ROW_BYTES)
#define STAGE_BYTES (A_STAGE_BYTES + B_STAGE_BYTES)
#define SMEM_TOTAL (NSTAGE * STAGE_BYTES)   // 61440

// ---------------- scratch (device globals; no allocs allowed) ----------------
__device__ float          g_act[(size_t)M_ROWS * N_BASAL];   // 256 MB approx activations
__device__ unsigned int   g_mask[N_BASAL];
__device__ __nv_bfloat16  g_A[(size_t)M_ROWS * K_PAD];       // bf16 image, padded
__device__ __nv_bfloat16  g_B[(size_t)N_BASAL * K_PAD];      // bf16 proj^T, padded
__device__ float          g_Bt[(size_t)N_BASAL * K_DIM];     // fp32 proj^T (rescore)

// ---------------- asm helpers ----------------
__device__ __forceinline__ uint32_t smem_u32(const void* p) {
    uint32_t a;
    asm("{ .reg .u64 t; cvta.to.shared.u64 t, %1; cvt.u32.u64 %0, t; }" : "=r"(a) : "l"(p));
    return a;
}
__device__ __forceinline__ void cp_async16(uint32_t dst, const void* src) {
    asm volatile("cp.async.cg.shared.global [%0], [%1], 16;" :: "r"(dst), "l"(src) : "memory");
}
__device__ __forceinline__ void cp_commit() {
    asm volatile("cp.async.commit_group;" ::: "memory");
}
template <int N>
__device__ __forceinline__ void cp_wait() {
    asm volatile("cp.async.wait_group %0;" :: "n"(N) : "memory");
}
__device__ __forceinline__ void ldm_x4(uint32_t* r, uint32_t addr) {
    asm volatile("ldmatrix.sync.aligned.m8n8.x4.shared.b16 {%0,%1,%2,%3}, [%4];"
                 : "=r"(r[0]), "=r"(r[1]), "=r"(r[2]), "=r"(r[3]) : "r"(addr));
}
__device__ __forceinline__ void mma_bf16(float* c, const uint32_t* a, uint32_t b0, uint32_t b1) {
    asm volatile("mma.sync.aligned.m16n8k16.row.col.f32.bf16.bf16.f32 "
                 "{%0,%1,%2,%3}, {%4,%5,%6,%7}, {%8,%9}, {%0,%1,%2,%3};"
                 : "+f"(c[0]), "+f"(c[1]), "+f"(c[2]), "+f"(c[3])
                 : "r"(a[0]), "r"(a[1]), "r"(a[2]), "r"(a[3]), "r"(b0), "r"(b1));
}

// ---------------------------------------------------------------------------
// pack synapses into bitmasks
// ---------------------------------------------------------------------------
__global__ void pack_syn_kernel(const float* __restrict__ syn) {
    int j = blockIdx.x * blockDim.x + threadIdx.x;
    if (j < N_BASAL) {
        unsigned int m = 0;
#pragma unroll
        for (int c = 0; c < NUM_CLS; ++c)
            m |= (syn[c * N_BASAL + j] > 0.5f) ? (1u << c) : 0u;
        g_mask[j] = m;
    }
}

// ---------------------------------------------------------------------------
// A: bf16(image), K padded with zeros
// ---------------------------------------------------------------------------
__global__ void conv_a_kernel(const float* __restrict__ img) {
    size_t idx = (size_t)blockIdx.x * 256 + threadIdx.x;   // 4096*800
    int m = (int)(idx / K_PAD);
    int k = (int)(idx % K_PAD);
    g_A[idx] = (k < K_DIM) ? __float2bfloat16(img[(size_t)m * K_DIM + k])
                           : __float2bfloat16(0.0f);
}

// ---------------------------------------------------------------------------
// B: transpose proj -> bf16 g_B [n][K_PAD] and fp32 g_Bt [n][K_DIM]
// ---------------------------------------------------------------------------
__global__ void conv_b_kernel(const float* __restrict__ proj) {
    __shared__ float t[32][33];
    int k0 = blockIdx.x * 32, n0 = blockIdx.y * 32;
    int tx = threadIdx.x, ty = threadIdx.y;   // 32 x 8
#pragma unroll
    for (int i = 0; i < 32; i += 8) {
        int kk = k0 + ty + i;
        t[ty + i][tx] = (kk < K_DIM) ? proj[(size_t)kk * N_BASAL + n0 + tx] : 0.0f;
    }
    __syncthreads();
#pragma unroll
    for (int i = 0; i < 32; i += 8) {
        int n = n0 + ty + i;
        int k = k0 + tx;
        if (k < K_PAD) {
            float v = t[tx][ty + i];
            g_B[(size_t)n * K_PAD + k] = __float2bfloat16(v);
            if (k < K_DIM) g_Bt[(size_t)n * K_DIM + k] = v;
        }
    }
}

// ---------------------------------------------------------------------------
// mma.sync bf16 GEMM: g_act[M,N] = g_A[M,Kp] * g_B[N,Kp]^T  (fp32 accum)
// ---------------------------------------------------------------------------
__global__ __launch_bounds__(256, 2)
void gemm_mma_kernel() {
    extern __shared__ char smem[];
    const uint32_t sb = smem_u32(smem);
    const int tid = threadIdx.x;
    const int lane = tid & 31;
    const int wid = tid >> 5;
    const int warpM = wid >> 2;
    const int warpN = wid & 3;
    const int m0 = blockIdx.y * BM;
    const int n0 = blockIdx.x * BN;

    const char* Abase = (const char*)g_A + (size_t)m0 * (K_PAD * 2);
    const char* Bbase = (const char*)g_B + (size_t)n0 * (K_PAD * 2);

    const int ar = tid >> 2;
    const int ac = tid & 3;

    auto load_stage = [&](int c, int s) {
        const uint32_t st = sb + s * STAGE_BYTES;
        const size_t koff = (size_t)c * (BK * 2);
        cp_async16(st + ar * ROW_BYTES + ac * 16,
                   Abase + (size_t)ar * (K_PAD * 2) + koff + ac * 16);
        cp_async16(st + (ar + 64) * ROW_BYTES + ac * 16,
                   Abase + (size_t)(ar + 64) * (K_PAD * 2) + koff + ac * 16);
        const uint32_t stB = st + A_STAGE_BYTES;
        cp_async16(stB + ar * ROW_BYTES + ac * 16,
                   Bbase + (size_t)ar * (K_PAD * 2) + koff + ac * 16);
        cp_async16(stB + (ar + 64) * ROW_BYTES + ac * 16,
                   Bbase + (size_t)(ar + 64) * (K_PAD * 2) + koff + ac * 16);
        cp_commit();
    };

    float acc[4][4][4];
#pragma unroll
    for (int i = 0; i < 4; ++i)
#pragma unroll
        for (int j = 0; j < 4; ++j)
#pragma unroll
            for (int q = 0; q < 4; ++q) acc[i][j][q] = 0.0f;

    const int lrow = lane & 15;
    const int lcol16 = (lane >> 4) << 4;

    load_stage(0, 0);
    load_stage(1, 1);

    for (int c = 0; c < NCHUNK; ++c) {
        const int s = c % NSTAGE;
        cp_wait<NSTAGE - 2>();
        __syncthreads();
        if (c + 2 < NCHUNK) load_stage(c + 2, (c + 2) % NSTAGE);

        const uint32_t stA = sb + s * STAGE_BYTES;
        const uint32_t stB = stA + A_STAGE_BYTES;
#pragma unroll
        for (int ks = 0; ks < 2; ++ks) {
            const int kbyte = ks * 32 + lcol16;
            uint32_t af[4][4];
#pragma unroll
            for (int mt = 0; mt < 4; ++mt)
                ldm_x4(af[mt], stA + (warpM * 64 + mt * 16 + lrow) * ROW_BYTES + kbyte);
            uint32_t bf[2][4];
#pragma unroll
            for (int nt = 0; nt < 2; ++nt)
                ldm_x4(bf[nt], stB + (warpN * 32 + nt * 16 + lrow) * ROW_BYTES + kbyte);
#pragma unroll
            for (int mt = 0; mt < 4; ++mt) {
#pragma unroll
                for (int n8 = 0; n8 < 4; ++n8) {
                    const int nt = n8 >> 1, hi = n8 & 1;
                    mma_bf16(acc[mt][n8], af[mt], bf[nt][hi], bf[nt][hi + 2]);
                }
            }
        }
        __syncthreads();
    }

    const int grp = lane >> 2;
    const int tj  = lane & 3;
#pragma unroll
    for (int mt = 0; mt < 4; ++mt) {
#pragma unroll
        for (int n8 = 0; n8 < 4; ++n8) {
            const int row = m0 + warpM * 64 + mt * 16 + grp;
            const int col = n0 + warpN * 32 + n8 * 8 + tj * 2;
            float* p0 = g_act + (size_t)row * N_BASAL + col;
            float* p1 = g_act + (size_t)(row + 8) * N_BASAL + col;
            *(float2*)p0 = make_float2(acc[mt][n8][0], acc[mt][n8][1]);
            *(float2*)p1 = make_float2(acc[mt][n8][2], acc[mt][n8][3]);
        }
    }
}

// ---------------------------------------------------------------------------
// select + overlap, two-tier: radix-select approx threshold, margin-classify,
// exact fp32 re-score of in-window candidates, exact rank, mask accumulate.
// One block (256 threads = 8 warps) per row.
// ---------------------------------------------------------------------------
__device__ __forceinline__ unsigned int f2key(float f) {
    unsigned int u = __float_as_uint(f);
    return (u & 0x80000000u) ? ~u : (u | 0x80000000u);
}
__device__ __forceinline__ float key2f(unsigned int k) {
    unsigned int u = (k & 0x80000000u) ? (k & 0x7FFFFFFFu) : ~k;
    return __uint_as_float(u);
}

__global__ __launch_bounds__(256)
void select_overlap_kernel(const float* __restrict__ img, float* __restrict__ out) {
    const int row = blockIdx.x;
    const float* a = g_act + (size_t)row * N_BASAL;
    const int tid = threadIdx.x;
    const int lane = tid & 31;
    const int wid = tid >> 5;

    __shared__ unsigned int hist[2048];
    __shared__ unsigned int segsum[256];
    __shared__ unsigned int s_kk, s_prefix;
    __shared__ int ov[NUM_CLS];
    __shared__ int s_ncand, s_nsure;
    __shared__ int   cand_idx[MAXC];
    __shared__ float cand_val[MAXC];

    if (tid == 0) { s_kk = NUM_ACT; s_prefix = 0; s_ncand = 0; s_nsure = 0; }
    if (tid < NUM_CLS) ov[tid] = 0;
    __syncthreads();

    // ---- 3 radix passes: find key of k-th largest approx value ----
    for (int p = 0; p < 3; ++p) {
        const int nbins = (p == 2) ? 1024 : 2048;
        for (int i = tid; i < nbins; i += 256) hist[i] = 0;
        __syncthreads();
        const unsigned int prefix = s_prefix;

        for (int j = tid; j < N_BASAL; j += 256) {
            unsigned int key = f2key(a[j]);
            unsigned int d; bool ok;
            if (p == 0)      { ok = true;                    d = key >> 21; }
            else if (p == 1) { ok = ((key >> 21) == prefix); d = (key >> 10) & 2047u; }
            else             { ok = ((key >> 10) == prefix); d = key & 1023u; }
            if (ok) atomicAdd(&hist[d], 1u);
        }
        __syncthreads();

        const int seg = nbins / 256;
        unsigned int ssum = 0;
        for (int i = 0; i < seg; ++i) ssum += hist[nbins - 1 - (tid * seg + i)];
        segsum[tid] = ssum;
        __syncthreads();

        if (tid == 0) {
            unsigned int kk = s_kk, before = 0;
            int selseg = 255;
            for (int t = 0; t < 256; ++t) {
                if (before + segsum[t] >= kk) { selseg = t; break; }
                before += segsum[t];
            }
            int selbin = 0;
            for (int i = 0; i < seg; ++i) {
                int b = nbins - 1 - (selseg * seg + i);
                unsigned int cc = hist[b];
                if (before + cc >= kk) { selbin = b; break; }
                before += cc;
            }
            s_kk = kk - before;
            if (p == 0)      s_prefix = (unsigned int)selbin;
            else if (p == 1) s_prefix = (prefix << 11) | (unsigned int)selbin;
            else             s_prefix = (prefix << 10) | (unsigned int)selbin;
        }
        __syncthreads();
    }

    const float tauf = key2f(s_prefix);
    const float hicut = tauf + 2.0f * DELTA;
    const float locut = tauf - 2.0f * DELTA;

    // ---- classification pass ----
    int cnt[NUM_CLS];
#pragma unroll
    for (int c = 0; c < NUM_CLS; ++c) cnt[c] = 0;
    int nsure = 0;

    for (int j = tid; j < N_BASAL; j += 256) {
        float v = a[j];
        if (v > hicut) {
            unsigned int m = g_mask[j];
#pragma unroll
            for (int c = 0; c < NUM_CLS; ++c) cnt[c] += (m >> c) & 1u;
            ++nsure;
        } else if (v >= locut) {
            int p = atomicAdd(&s_ncand, 1);
            if (p < MAXC) cand_idx[p] = j;
        }
    }
    atomicAdd(&s_nsure, nsure);
    __syncthreads();

    const int C = (s_ncand < MAXC) ? s_ncand : MAXC;
    const int k_remain = NUM_ACT - s_nsure;

    // ---- exact fp32 re-score: one warp per candidate, round robin ----
    const float* irow = img + (size_t)row * K_DIM;
    for (int c = wid; c < C; c += 8) {
        const float* brow = g_Bt + (size_t)cand_idx[c] * K_DIM;
        float s = 0.0f;
        for (int k = lane; k < K_DIM; k += 32)
            s = fmaf(irow[k], brow[k], s);
#pragma unroll
        for (int o = 16; o > 0; o >>= 1)
            s += __shfl_xor_sync(0xFFFFFFFFu, s, o);
        if (lane == 0) cand_val[c] = s;
    }
    __syncthreads();

    // ---- exact rank among candidates (value desc, index asc) ----
    for (int c = tid; c < C; c += 256) {
        const float vc = cand_val[c];
        const int ic = cand_idx[c];
        int rank = 0;
        for (int d = 0; d < C; ++d) {
            float vd = cand_val[d];
            rank += (vd > vc || (vd == vc && cand_idx[d] < ic)) ? 1 : 0;
        }
        if (rank < k_remain) {
            unsigned int m = g_mask[ic];
#pragma unroll
            for (int cc = 0; cc < NUM_CLS; ++cc) cnt[cc] += (m >> cc) & 1u;
        }
    }

#pragma unroll
    for (int c = 0; c < NUM_CLS; ++c)
        if (cnt[c]) atomicAdd(&ov[c], cnt[c]);
    __syncthreads();

    if (tid < NUM_CLS)
        out[row * NUM_CLS + tid] = (float)ov[tid];
}

// ---------------------------------------------------------------------------
// Launch
// ---------------------------------------------------------------------------
extern "C" void kernel_launch(void* const* d_in, const int* in_sizes, int n_in,
                              void* d_out, int out_size) {
    const float* image = (const float*)d_in[0];   // [4096, 784]
    const float* proj  = (const float*)d_in[1];   // [784, 16384]
    const float* syn   = (const float*)d_in[2];   // [10, 16384]
    float* out = (float*)d_out;                   // [4096, 10]

    cudaFuncSetAttribute(gemm_mma_kernel, cudaFuncAttributeMaxDynamicSharedMemorySize, SMEM_TOTAL);

    pack_syn_kernel<<<(N_BASAL + 255) / 256, 256>>>(syn);
    conv_a_kernel<<<(int)(((size_t)M_ROWS * K_PAD) / 256), 256>>>(image);
    {
        dim3 grid(K_PAD / 32, N_BASAL / 32);      // 25 x 512
        conv_b_kernel<<<grid, dim3(32, 8)>>>(proj);
    }
    {
        dim3 grid(N_BASAL / BN, M_ROWS / BM);     // 128 x 32
        gemm_mma_kernel<<<grid, 256, SMEM_TOTAL>>>();
    }
    select_overlap_kernel<<<M_ROWS, 256>>>(image, out);
}